// round 13
// baseline (speedup 1.0000x reference)
#include <cuda_runtime.h>
#include <cuda_bf16.h>
#include <cstdint>

// DepthSeparableConv2d_conv3_4: dw3x3+BN1+ReLU+cut(4.0) -> pw1x1+BN2+ReLU+cut(0.001)
// B=32, C=O=256, H=W=56. Three kernels: dw -> compact -> pw.
// dw v4: 4x4 tile/thread from a 6x6 global window, NO out[] storage —
// pass 1 computes only the plane max (values die in-register); surviving
// planes (~1%) recompute+store from the still-live window. v3's regs=50
// with ~70-reg live set was spilling (L1=57.6% was LDL/STL); v4's live set
// ~55 regs under a __launch_bounds__(224,4) cap of 73 -> zero spills.
// (Resubmission — previous run died to the recurring infra flake; kernels
//  renamed _v5 as a hedge against content-keyed caching.)

#define Bn   32
#define Cn   256
#define On   256
#define Hn   56
#define Wn   56
#define HW   3136           // 56*56
#define HW4  784            // HW/4
#define EPS  1e-5f
#define DW_THR 4.0f
#define PW_THR 0.001f
#define TO   8              // output channels per pw block

__device__ float g_y[(size_t)Bn * Cn * HW];
__device__ int   g_flags[Bn * Cn];
__device__ int   g_slist[Bn * Cn];   // per-batch survivor channel ids (ascending)
__device__ int   g_scount[Bn];

// ---------------------------------------------------------------------------
// Kernel A: depthwise 3x3 + BN1-folded + ReLU + plane max; recompute-on-keep.
// One block per (b,c) plane; 224 threads, 196 active (14x14 grid of 4x4 tiles).
// ---------------------------------------------------------------------------
__global__ __launch_bounds__(224, 4)
void dw_kernel_v5(const float* __restrict__ x,
                  const float* __restrict__ dw_w,   // [C,1,3,3]
                  const float* __restrict__ dw_b,   // [C]
                  const float* __restrict__ g1, const float* __restrict__ b1,
                  const float* __restrict__ m1, const float* __restrict__ v1)
{
    const int plane = blockIdx.x;          // b*Cn + c
    const int c     = plane & (Cn - 1);
    const int tid   = threadIdx.x;
    const int lane  = tid & 31, warp = tid >> 5;

    const bool active = (tid < 196);
    const int g  = tid % 14;               // column group (4 cols each)
    const int s  = tid / 14;               // row strip   (4 rows each)
    const int c0 = g * 4;
    const int r0 = s * 4;

    // BN1 folded into weights: r = relu( sum (w*inv)*x + (bias*inv + add) )
    const float inv = g1[c] * rsqrtf(v1[c] + EPS);
    float wf[9];
#pragma unroll
    for (int k = 0; k < 9; k++) wf[k] = dw_w[c * 9 + k] * inv;
    const float badd = fmaf(dw_b[c], inv, b1[c] - m1[c] * inv);

    const float* __restrict__ xp = x + (size_t)plane * HW;

    // Load 6x6 input window (rows r0-1..r0+4, cols c0-1..c0+4), zero padded.
    float v[6][6];
#pragma unroll
    for (int j = 0; j < 6; j++) {
        const int r = r0 - 1 + j;
        const bool rOk = active && ((unsigned)r < (unsigned)Hn);
        const float* rp = xp + r * Wn;
        float4 ctr = make_float4(0.f, 0.f, 0.f, 0.f);
        float lf = 0.f, rt = 0.f;
        if (rOk) {
            ctr = *(const float4*)(rp + c0);          // 16B-aligned
            if (g > 0)  lf = rp[c0 - 1];
            if (g < 13) rt = rp[c0 + 4];
        }
        v[j][0] = lf;    v[j][1] = ctr.x; v[j][2] = ctr.y;
        v[j][3] = ctr.z; v[j][4] = ctr.w; v[j][5] = rt;
    }

    // Pass 1: raw max only (relu folded: plane max of relu'd = fmax(0, rawmax)).
    float mxr = -1e30f;
#pragma unroll
    for (int i = 0; i < 4; i++) {
#pragma unroll
        for (int k = 0; k < 4; k++) {
            float a = badd;
#pragma unroll
            for (int dr = 0; dr < 3; dr++)
#pragma unroll
                for (int dc = 0; dc < 3; dc++)
                    a = fmaf(wf[dr * 3 + dc], v[i + dr][k + dc], a);
            mxr = fmaxf(mxr, a);
        }
    }
    float mx = active ? fmaxf(mxr, 0.0f) : 0.0f;

    // Block max over 7 warps.
    __shared__ float smax[7];
    __shared__ int   s_keep;
#pragma unroll
    for (int off = 16; off; off >>= 1)
        mx = fmaxf(mx, __shfl_xor_sync(0xffffffffu, mx, off));
    if (lane == 0) smax[warp] = mx;
    __syncthreads();
    if (tid == 0) {
        float m = smax[0];
#pragma unroll
        for (int q = 1; q < 7; q++) m = fmaxf(m, smax[q]);
        int keep = (m >= DW_THR) ? 1 : 0;
        s_keep = keep;
        g_flags[plane] = keep;
    }
    __syncthreads();

    // Pass 2 (rare): recompute from the still-live window and store.
    if (s_keep && active) {
        float* __restrict__ yp = g_y + (size_t)plane * HW + c0;
#pragma unroll
        for (int i = 0; i < 4; i++) {
            float o0 = badd, o1 = badd, o2 = badd, o3 = badd;
#pragma unroll
            for (int dr = 0; dr < 3; dr++)
#pragma unroll
                for (int dc = 0; dc < 3; dc++) {
                    const float wv = wf[dr * 3 + dc];
                    o0 = fmaf(wv, v[i + dr][0 + dc], o0);
                    o1 = fmaf(wv, v[i + dr][1 + dc], o1);
                    o2 = fmaf(wv, v[i + dr][2 + dc], o2);
                    o3 = fmaf(wv, v[i + dr][3 + dc], o3);
                }
            *(float4*)(yp + (r0 + i) * Wn) =
                make_float4(fmaxf(o0, 0.f), fmaxf(o1, 0.f),
                            fmaxf(o2, 0.f), fmaxf(o3, 0.f));
        }
    }
}

// ---------------------------------------------------------------------------
// Kernel B: per-batch survivor-list compaction. One block per batch.
// ---------------------------------------------------------------------------
__global__ __launch_bounds__(256)
void compact_kernel_v5()
{
    const int b   = blockIdx.x;
    const int tid = threadIdx.x;
    const int lane = tid & 31, warp = tid >> 5;
    __shared__ int warpcnt[8];

    const int f = g_flags[b * Cn + tid];
    unsigned ball = __ballot_sync(0xffffffffu, f);
    if (lane == 0) warpcnt[warp] = __popc(ball);
    __syncthreads();
    int prefix = 0;
#pragma unroll
    for (int q = 0; q < 8; q++) prefix += (q < warp) ? warpcnt[q] : 0;
    if (f)
        g_slist[b * Cn + prefix + __popc(ball & ((1u << lane) - 1u))] = tid;
    if (tid == 0) {
        int n = 0;
#pragma unroll
        for (int q = 0; q < 8; q++) n += warpcnt[q];
        g_scount[b] = n;
    }
}

// ---------------------------------------------------------------------------
// Kernel C: pointwise over survivors, TO=8 o's per block, precomputed list,
// write-through z stores. (Round-8/11 measured version, unchanged.)
// ---------------------------------------------------------------------------
__global__ __launch_bounds__(256)
void pw_kernel_v5(const float* __restrict__ pw_w,   // [O,C]
                  const float* __restrict__ pw_b,   // [O]
                  const float* __restrict__ g2, const float* __restrict__ b2,
                  const float* __restrict__ m2, const float* __restrict__ v2,
                  float* __restrict__ z)
{
    const int b   = blockIdx.x >> 5;            // 32 o-groups per batch
    const int og  = (blockIdx.x & 31) * TO;
    const int tid = threadIdx.x;
    const int lane = tid & 31, warp = tid >> 5;

    __shared__ int   soff4[Cn];
    __shared__ float sw[Cn * TO];
    __shared__ float sbias[TO], sinv[TO], sadd[TO];
    __shared__ float swmax[8][TO];
    __shared__ int   skeep[TO];

    const int n = g_scount[b];
    if (tid < n) {
        int c = g_slist[b * Cn + tid];
        soff4[tid] = c * HW4;
#pragma unroll
        for (int t = 0; t < TO; t++)
            sw[tid * TO + t] = pw_w[(og + t) * Cn + c];
    }
    if (tid < TO) {
        int o = og + tid;
        float iv = g2[o] * rsqrtf(v2[o] + EPS);
        sbias[tid] = pw_b[o];
        sinv[tid]  = iv;
        sadd[tid]  = b2[o] - m2[o] * iv;
    }
    __syncthreads();

    const float4* __restrict__ yb4 = (const float4*)(g_y + (size_t)b * Cn * HW);
    float4* __restrict__ z4 = (float4*)z;
    const size_t zbase = (size_t)(b * On + og) * HW4;

    float mx[TO];
#pragma unroll
    for (int t = 0; t < TO; t++) mx[t] = 0.0f;

#pragma unroll
    for (int it = 0; it < 4; it++) {
        int idx = tid + it * 256;
        if (idx < HW4) {
            float4 acc[TO];
#pragma unroll
            for (int t = 0; t < TO; t++) {
                float bv = sbias[t];
                acc[t] = make_float4(bv, bv, bv, bv);
            }
            for (int j = 0; j < n; j++) {
                float4 yv = yb4[soff4[j] + idx];
                const float* wj = &sw[j * TO];
#pragma unroll
                for (int t = 0; t < TO; t++) {
                    float wv = wj[t];
                    acc[t].x = fmaf(wv, yv.x, acc[t].x);
                    acc[t].y = fmaf(wv, yv.y, acc[t].y);
                    acc[t].z = fmaf(wv, yv.z, acc[t].z);
                    acc[t].w = fmaf(wv, yv.w, acc[t].w);
                }
            }
#pragma unroll
            for (int t = 0; t < TO; t++) {
                float iv = sinv[t], ad = sadd[t];
                float4 r;
                r.x = fmaxf(fmaf(acc[t].x, iv, ad), 0.0f);
                r.y = fmaxf(fmaf(acc[t].y, iv, ad), 0.0f);
                r.z = fmaxf(fmaf(acc[t].z, iv, ad), 0.0f);
                r.w = fmaxf(fmaf(acc[t].w, iv, ad), 0.0f);
                mx[t] = fmaxf(mx[t], fmaxf(fmaxf(r.x, r.y), fmaxf(r.z, r.w)));
                __stwt(&z4[zbase + (size_t)t * HW4 + idx], r);
            }
        }
    }

#pragma unroll
    for (int t = 0; t < TO; t++) {
        float m = mx[t];
#pragma unroll
        for (int off = 16; off; off >>= 1)
            m = fmaxf(m, __shfl_xor_sync(0xffffffffu, m, off));
        if (lane == 0) swmax[warp][t] = m;
    }
    __syncthreads();
    if (tid < TO) {
        float m = swmax[0][tid];
#pragma unroll
        for (int i = 1; i < 8; i++) m = fmaxf(m, swmax[i][tid]);
        skeep[tid] = (m > 0.0f && m < PW_THR) ? 1 : 0;
    }
    __syncthreads();

    const float4 zero4 = make_float4(0.f, 0.f, 0.f, 0.f);
#pragma unroll
    for (int t = 0; t < TO; t++) {
        if (skeep[t]) {
#pragma unroll
            for (int it = 0; it < 4; it++) {
                int idx = tid + it * 256;
                if (idx < HW4)
                    __stwt(&z4[zbase + (size_t)t * HW4 + idx], zero4);
            }
        }
    }
}

// ---------------------------------------------------------------------------
extern "C" void kernel_launch(void* const* d_in, const int* in_sizes, int n_in,
                              void* d_out, int out_size)
{
    const float* x    = (const float*)d_in[0];
    const float* dw_w = (const float*)d_in[1];
    const float* dw_b = (const float*)d_in[2];
    const float* pw_w = (const float*)d_in[3];
    const float* pw_b = (const float*)d_in[4];
    const float* g1   = (const float*)d_in[5];
    const float* b1   = (const float*)d_in[6];
    const float* m1   = (const float*)d_in[7];
    const float* v1   = (const float*)d_in[8];
    const float* g2   = (const float*)d_in[9];
    const float* b2   = (const float*)d_in[10];
    const float* m2   = (const float*)d_in[11];
    const float* v2   = (const float*)d_in[12];
    float* z = (float*)d_out;

    dw_kernel_v5<<<Bn * Cn, 224>>>(x, dw_w, dw_b, g1, b1, m1, v1);
    compact_kernel_v5<<<Bn, 256>>>();
    pw_kernel_v5<<<Bn * (On / TO), 256>>>(pw_w, pw_b, g2, b2, m2, v2, z);
}